// round 2
// baseline (speedup 1.0000x reference)
#include <cuda_runtime.h>
#include <math.h>
#include <float.h>

#define N 8192
#define D 128
#define BM 128                 // anchor rows per block
#define BN 128                 // cols per j-tile
#define NSPLIT 2               // column splits (grid.y)
#define COLS_PER_SPLIT (N / NSPLIT)
#define NTILES (COLS_PER_SPLIT / BN)
#define TSTRIDE 132            // padded shared stride (floats), float4-aligned
#define MARGIN 0.05f

// Scratch (allocation-free rule: __device__ globals)
__device__ float g_xn[N * D];
__device__ float g_sq[N];
__device__ float g_vmaxpos[NSPLIT][N];
__device__ float g_vminneg[NSPLIT][N];

// ---------------------------------------------------------------------------
// Kernel 1: L2-normalize rows; also store sum of squares of the stored
// (rounded) normalized values, matching the reference's sq computation.
// One warp per row.
__global__ void normalize_kernel(const float* __restrict__ x) {
    int row  = blockIdx.x * 8 + (threadIdx.x >> 5);
    int lane = threadIdx.x & 31;
    float4 v = ((const float4*)(x + (size_t)row * D))[lane];
    float s = v.x * v.x + v.y * v.y + v.z * v.z + v.w * v.w;
#pragma unroll
    for (int o = 16; o; o >>= 1) s += __shfl_xor_sync(0xffffffffu, s, o);
    float r = 1.0f / fmaxf(sqrtf(s), 1e-12f);
    float4 o4 = make_float4(v.x * r, v.y * r, v.z * r, v.w * r);
    ((float4*)(g_xn + (size_t)row * D))[lane] = o4;
    float s2 = o4.x * o4.x + o4.y * o4.y + o4.z * o4.z + o4.w * o4.w;
#pragma unroll
    for (int o = 16; o; o >>= 1) s2 += __shfl_xor_sync(0xffffffffu, s2, o);
    if (lane == 0) g_sq[row] = s2;
}

// ---------------------------------------------------------------------------
// Kernel 2: fused GEMM + batch-hard mining.
// Each block: 128 anchor rows x COLS_PER_SPLIT cols.
// Per thread: 8x8 microtile. Shared tiles stored K-major [k][row], stride 132.
// Tracks per-row: max over positives / min over negatives of v = sq_j - 2*dot.
extern __shared__ float smem_dyn[];

__global__ __launch_bounds__(256, 1)
void tile_kernel(const int* __restrict__ labels) {
    float* As = smem_dyn;                         // [D][TSTRIDE]
    float* Bs = smem_dyn + D * TSTRIDE;           // [D][TSTRIDE]
    int*   collab = (int*)(smem_dyn + 2 * D * TSTRIDE);   // [BN]
    float* colsq  = (float*)(collab + BN);                // [BN]

    const int t    = threadIdx.x;
    const int lane = t & 31;
    const int w    = t >> 5;
    const int tx   = t & 15;     // col group (8 cols each)
    const int ty   = t >> 4;     // row group (8 rows each)
    const int rowBase      = blockIdx.x * BM;
    const int colSplitBase = blockIdx.y * COLS_PER_SPLIT;

    // Load A tile once: As[k][row]. Global: each lane reads one row's float4
    // (k-quad fixed per warp) -> scattered 16B reads, all L2-resident.
    // Shared stores: addr = const + lane -> conflict-free.
#pragma unroll
    for (int g = 0; g < 4; g++) {
        int row = g * 32 + lane;
#pragma unroll
        for (int i = 0; i < 4; i++) {
            int kq = i * 8 + w;
            float4 v = ((const float4*)(g_xn + (size_t)(rowBase + row) * D))[kq];
            As[(kq * 4 + 0) * TSTRIDE + row] = v.x;
            As[(kq * 4 + 1) * TSTRIDE + row] = v.y;
            As[(kq * 4 + 2) * TSTRIDE + row] = v.z;
            As[(kq * 4 + 3) * TSTRIDE + row] = v.w;
        }
    }

    int rowlab[8];
#pragma unroll
    for (int r = 0; r < 8; r++) rowlab[r] = labels[rowBase + ty * 8 + r];

    float vmaxpos[8], vminneg[8];
#pragma unroll
    for (int r = 0; r < 8; r++) { vmaxpos[r] = -FLT_MAX; vminneg[r] = FLT_MAX; }

    for (int jt = 0; jt < NTILES; jt++) {
        const int colBase = colSplitBase + jt * BN;
        __syncthreads();   // protect Bs/collab from previous iteration's readers

        // Load B tile: Bs[k][col]
#pragma unroll
        for (int g = 0; g < 4; g++) {
            int col = g * 32 + lane;
#pragma unroll
            for (int i = 0; i < 4; i++) {
                int kq = i * 8 + w;
                float4 v = ((const float4*)(g_xn + (size_t)(colBase + col) * D))[kq];
                Bs[(kq * 4 + 0) * TSTRIDE + col] = v.x;
                Bs[(kq * 4 + 1) * TSTRIDE + col] = v.y;
                Bs[(kq * 4 + 2) * TSTRIDE + col] = v.z;
                Bs[(kq * 4 + 3) * TSTRIDE + col] = v.w;
            }
        }
        if (t < BN) {
            collab[t] = labels[colBase + t];
            colsq[t]  = g_sq[colBase + t];
        }
        __syncthreads();

        float acc[8][8];
#pragma unroll
        for (int r = 0; r < 8; r++)
#pragma unroll
            for (int c = 0; c < 8; c++) acc[r][c] = 0.0f;

#pragma unroll 4
        for (int k = 0; k < D; k++) {
            float4 a0 = *(const float4*)&As[k * TSTRIDE + ty * 8];
            float4 a1 = *(const float4*)&As[k * TSTRIDE + ty * 8 + 4];
            float4 b0 = *(const float4*)&Bs[k * TSTRIDE + tx * 8];
            float4 b1 = *(const float4*)&Bs[k * TSTRIDE + tx * 8 + 4];
            float a[8] = {a0.x, a0.y, a0.z, a0.w, a1.x, a1.y, a1.z, a1.w};
            float b[8] = {b0.x, b0.y, b0.z, b0.w, b1.x, b1.y, b1.z, b1.w};
#pragma unroll
            for (int r = 0; r < 8; r++)
#pragma unroll
                for (int c = 0; c < 8; c++)
                    acc[r][c] = fmaf(a[r], b[c], acc[r][c]);
        }

        // Epilogue: masked running max/min on v = sq_j - 2*dot
#pragma unroll
        for (int c = 0; c < 8; c++) {
            int   colg = colBase + tx * 8 + c;
            int   cl   = collab[tx * 8 + c];
            float sqj  = colsq[tx * 8 + c];
#pragma unroll
            for (int r = 0; r < 8; r++) {
                float v = fmaf(-2.0f, acc[r][c], sqj);
                int rowg = rowBase + ty * 8 + r;
                if (rowlab[r] == cl) {
                    if (colg != rowg) vmaxpos[r] = fmaxf(vmaxpos[r], v);
                } else {
                    vminneg[r] = fminf(vminneg[r], v);
                }
            }
        }
    }

    // Cross-thread reduction: 16 tx-partials per row. Reuse As region.
    __syncthreads();
    float* redmax = smem_dyn;             // [BM][16]
    float* redmin = smem_dyn + BM * 16;   // [BM][16]
#pragma unroll
    for (int r = 0; r < 8; r++) {
        redmax[(ty * 8 + r) * 16 + tx] = vmaxpos[r];
        redmin[(ty * 8 + r) * 16 + tx] = vminneg[r];
    }
    __syncthreads();
    if (t < BM) {
        float mx = -FLT_MAX, mn = FLT_MAX;
#pragma unroll
        for (int i = 0; i < 16; i++) {
            mx = fmaxf(mx, redmax[t * 16 + i]);
            mn = fminf(mn, redmin[t * 16 + i]);
        }
        g_vmaxpos[blockIdx.y][rowBase + t] = mx;
        g_vminneg[blockIdx.y][rowBase + t] = mn;
    }
}

// ---------------------------------------------------------------------------
// Kernel 3: combine splits, per-anchor loss, AvgNonZero reduction.
__global__ void finalize_kernel(float* __restrict__ out) {
    __shared__ float ssum[1024];
    __shared__ int   scnt[1024];
    int t = threadIdx.x;
    float sum = 0.0f;
    int   cnt = 0;
    for (int i = t; i < N; i += 1024) {
        float mp = fmaxf(g_vmaxpos[0][i], g_vmaxpos[1][i]);
        float mn = fminf(g_vminneg[0][i], g_vminneg[1][i]);
        bool haspos = (mp > -FLT_MAX);
        bool hasneg = (mn <  FLT_MAX);
        if (haspos && hasneg) {
            float sqi = g_sq[i];
            float dap = sqrtf(fmaxf(sqi + mp, 0.0f));
            float dan = sqrtf(fmaxf(sqi + mn, 0.0f));
            float per = fmaxf(dap - dan + MARGIN, 0.0f);
            if (per > 0.0f) { sum += per; cnt++; }
        }
    }
    ssum[t] = sum; scnt[t] = cnt;
    __syncthreads();
    for (int o = 512; o; o >>= 1) {
        if (t < o) { ssum[t] += ssum[t + o]; scnt[t] += scnt[t + o]; }
        __syncthreads();
    }
    if (t == 0) out[0] = (scnt[0] > 0) ? (ssum[0] / (float)scnt[0]) : 0.0f;
}

// ---------------------------------------------------------------------------
extern "C" void kernel_launch(void* const* d_in, const int* in_sizes, int n_in,
                              void* d_out, int out_size) {
    const float* x      = (const float*)d_in[0];
    const int*   labels = (const int*)d_in[1];

    normalize_kernel<<<N / 8, 256>>>(x);

    size_t smem_bytes = (size_t)(2 * D * TSTRIDE) * sizeof(float)
                      + (size_t)BN * sizeof(int) + (size_t)BN * sizeof(float);
    cudaFuncSetAttribute(tile_kernel,
                         cudaFuncAttributeMaxDynamicSharedMemorySize,
                         (int)smem_bytes);
    tile_kernel<<<dim3(N / BM, NSPLIT), 256, smem_bytes>>>(labels);

    finalize_kernel<<<1, 1024>>>((float*)d_out);
}

// round 4
// speedup vs baseline: 2.8435x; 2.8435x over previous
#include <cuda_runtime.h>
#include <cuda_bf16.h>
#include <math.h>
#include <float.h>
#include <stdint.h>

#define N 8192
#define D 128
#define BM 128
#define BN 128
#define NSPLIT 2
#define COLS_PER_SPLIT (N / NSPLIT)
#define NTILES (COLS_PER_SPLIT / BN)
#define MARGIN 0.05f
#define TS 272              // smem tile row stride in bytes (128 bf16 + 8 pad)

// ---------------- device scratch ----------------
__device__ __nv_bfloat16 g_hi[N * D];
__device__ __nv_bfloat16 g_lo[N * D];
__device__ float g_sq[N];
__device__ float g_vmaxpos[NSPLIT][N];
__device__ float g_vminneg[NSPLIT][N];

// ---------------- smem layout (bytes) ----------------
#define TILE_BYTES (128 * TS)                     // 34816
#define SM_A_HI    0
#define SM_A_LO    TILE_BYTES
#define SM_B_HI(b) (2 * TILE_BYTES + (b) * 2 * TILE_BYTES)
#define SM_B_LO(b) (SM_B_HI(b) + TILE_BYTES)
#define SM_SQ(b)   (6 * TILE_BYTES + (b) * 512)   // float[128] per buf
#define SM_LAB(b)  (6 * TILE_BYTES + 1024 + (b) * 512)
#define SM_RED     (6 * TILE_BYTES + 2048)        // redmax[4][128], redmin[4][128]
#define SM_TOTAL   (SM_RED + 4096)

__device__ __forceinline__ uint32_t smem_u32(const void* p) {
    uint32_t a;
    asm("{ .reg .u64 t; cvta.to.shared.u64 t, %1; cvt.u32.u64 %0, t; }" : "=r"(a) : "l"(p));
    return a;
}
#define CP16(dst, src) \
    asm volatile("cp.async.cg.shared.global [%0], [%1], 16;" :: "r"(dst), "l"(src) : "memory")
#define CP_COMMIT() asm volatile("cp.async.commit_group;" ::: "memory")
#define CP_WAIT0()  asm volatile("cp.async.wait_group 0;" ::: "memory")

__device__ __forceinline__ void ldm_x4(uint32_t* r, uint32_t addr) {
    asm volatile("ldmatrix.sync.aligned.m8n8.x4.shared.b16 {%0,%1,%2,%3}, [%4];"
                 : "=r"(r[0]), "=r"(r[1]), "=r"(r[2]), "=r"(r[3]) : "r"(addr));
}
__device__ __forceinline__ void ldm_x2(uint32_t* r, uint32_t addr) {
    asm volatile("ldmatrix.sync.aligned.m8n8.x2.shared.b16 {%0,%1}, [%2];"
                 : "=r"(r[0]), "=r"(r[1]) : "r"(addr));
}
__device__ __forceinline__ void mma_bf16(float* c, const uint32_t* a, const uint32_t* b) {
    asm volatile(
        "mma.sync.aligned.m16n8k16.row.col.f32.bf16.bf16.f32 "
        "{%0,%1,%2,%3}, {%4,%5,%6,%7}, {%8,%9}, {%0,%1,%2,%3};"
        : "+f"(c[0]), "+f"(c[1]), "+f"(c[2]), "+f"(c[3])
        : "r"(a[0]), "r"(a[1]), "r"(a[2]), "r"(a[3]), "r"(b[0]), "r"(b[1]));
}

// ---------------------------------------------------------------------------
// Kernel 1: normalize rows, emit bf16 hi/lo split + fp32 sum-of-squares.
__global__ void normalize_kernel(const float* __restrict__ x) {
    int row  = blockIdx.x * 8 + (threadIdx.x >> 5);
    int lane = threadIdx.x & 31;
    float4 v = ((const float4*)(x + (size_t)row * D))[lane];
    float s = v.x * v.x + v.y * v.y + v.z * v.z + v.w * v.w;
#pragma unroll
    for (int o = 16; o; o >>= 1) s += __shfl_xor_sync(0xffffffffu, s, o);
    float r = 1.0f / fmaxf(sqrtf(s), 1e-12f);
    float o4[4] = {v.x * r, v.y * r, v.z * r, v.w * r};
    float s2 = o4[0]*o4[0] + o4[1]*o4[1] + o4[2]*o4[2] + o4[3]*o4[3];
#pragma unroll
    for (int o = 16; o; o >>= 1) s2 += __shfl_xor_sync(0xffffffffu, s2, o);
    if (lane == 0) g_sq[row] = s2;

    uint32_t hp[2], lp[2];
#pragma unroll
    for (int i = 0; i < 2; i++) {
        __nv_bfloat16 h0 = __float2bfloat16_rn(o4[2*i]);
        __nv_bfloat16 h1 = __float2bfloat16_rn(o4[2*i+1]);
        __nv_bfloat16 l0 = __float2bfloat16_rn(o4[2*i]   - __bfloat162float(h0));
        __nv_bfloat16 l1 = __float2bfloat16_rn(o4[2*i+1] - __bfloat162float(h1));
        hp[i] = (uint32_t)__bfloat16_as_ushort(h0) | ((uint32_t)__bfloat16_as_ushort(h1) << 16);
        lp[i] = (uint32_t)__bfloat16_as_ushort(l0) | ((uint32_t)__bfloat16_as_ushort(l1) << 16);
    }
    ((uint2*)(g_hi + (size_t)row * D))[lane] = make_uint2(hp[0], hp[1]);
    ((uint2*)(g_lo + (size_t)row * D))[lane] = make_uint2(lp[0], lp[1]);
}

// ---------------------------------------------------------------------------
// Kernel 2: HMMA (mma.sync bf16 hi/lo split) GEMM + fused batch-hard mining.
// 256 threads = 8 warps, warp grid 2m x 4n (warp tile 64x32).
__global__ __launch_bounds__(256, 1)
void tile_kernel(const int* __restrict__ labels) {
    extern __shared__ char smem[];
    const uint32_t sb = smem_u32(smem);
    const int tid  = threadIdx.x;
    const int lane = tid & 31;
    const int wid  = tid >> 5;
    const int wm   = wid & 1;          // 0..1  (64 rows each)
    const int wn   = wid >> 1;         // 0..3  (32 cols each)
    const int rowBase      = blockIdx.x * BM;
    const int split        = blockIdx.y;
    const int colSplitBase = split * COLS_PER_SPLIT;

    // ---- prologue: async-load A (hi/lo) ----
    {
        const char* sH = (const char*)g_hi + (size_t)rowBase * D * 2;
        const char* sL = (const char*)g_lo + (size_t)rowBase * D * 2;
#pragma unroll
        for (int i = 0; i < 8; i++) {
            int q = tid + i * 256;           // 2048 16B chunks per component
            int r = q >> 4, kc = q & 15;
            uint32_t off = r * TS + kc * 16;
            size_t   go  = (size_t)r * 256 + kc * 16;
            CP16(sb + SM_A_HI + off, sH + go);
            CP16(sb + SM_A_LO + off, sL + go);
        }
    }

    // B tile async loader (+ per-col meta)
    auto loadB = [&](int jt, int b) {
        int colBase = colSplitBase + jt * BN;
        const char* sH = (const char*)g_hi + (size_t)colBase * D * 2;
        const char* sL = (const char*)g_lo + (size_t)colBase * D * 2;
#pragma unroll
        for (int i = 0; i < 8; i++) {
            int q = tid + i * 256;
            int r = q >> 4, kc = q & 15;
            uint32_t off = r * TS + kc * 16;
            size_t   go  = (size_t)r * 256 + kc * 16;
            CP16(sb + SM_B_HI(b) + off, sH + go);
            CP16(sb + SM_B_LO(b) + off, sL + go);
        }
        if (tid < BN) {
            *(float*)(smem + SM_SQ(b)  + tid * 4) = g_sq[colBase + tid];
            *(int*)  (smem + SM_LAB(b) + tid * 4) = labels[colBase + tid];
        }
        CP_COMMIT();
    };

    loadB(0, 0);
    CP_WAIT0();
    __syncthreads();

    // per-thread row labels: rows = wm*64 + mt*16 + h*8 + lane/4
    int rowlab[4][2];
#pragma unroll
    for (int mt = 0; mt < 4; mt++)
#pragma unroll
        for (int h = 0; h < 2; h++)
            rowlab[mt][h] = labels[rowBase + wm * 64 + mt * 16 + h * 8 + (lane >> 2)];

    float vmax[4][2], vmin[4][2];
#pragma unroll
    for (int mt = 0; mt < 4; mt++)
#pragma unroll
        for (int h = 0; h < 2; h++) { vmax[mt][h] = -FLT_MAX; vmin[mt][h] = FLT_MAX; }

    // lane-dependent ldmatrix base offsets
    const uint32_t aLane = (uint32_t)((wm * 64 + (lane & 7) + ((lane >> 3) & 1) * 8) * TS
                                      + (lane >> 4) * 16);
    const int lane16 = lane & 15;
    const uint32_t bLane = (uint32_t)((wn * 32 + (lane16 & 7)) * TS + (lane16 >> 3) * 16);

    for (int jt = 0; jt < NTILES; jt++) {
        int b = jt & 1;
        if (jt + 1 < NTILES) loadB(jt + 1, b ^ 1);   // overlap with compute

        float acc[4][4][4];
#pragma unroll
        for (int mt = 0; mt < 4; mt++)
#pragma unroll
            for (int nt = 0; nt < 4; nt++)
#pragma unroll
                for (int i = 0; i < 4; i++) acc[mt][nt][i] = 0.0f;

        const uint32_t AH = sb + SM_A_HI, AL = sb + SM_A_LO;
        const uint32_t BH = sb + SM_B_HI(b), BL = sb + SM_B_LO(b);

#pragma unroll
        for (int ks = 0; ks < 8; ks++) {
            uint32_t aH[4][4], aL[4][4], bH[4][2], bL[4][2];
#pragma unroll
            for (int mt = 0; mt < 4; mt++) {
                uint32_t off = aLane + (uint32_t)(mt * 16 * TS + ks * 32);
                ldm_x4(aH[mt], AH + off);
                ldm_x4(aL[mt], AL + off);
            }
#pragma unroll
            for (int nt = 0; nt < 4; nt++) {
                uint32_t off = bLane + (uint32_t)(nt * 8 * TS + ks * 32);
                ldm_x2(bH[nt], BH + off);
                ldm_x2(bL[nt], BL + off);
            }
#pragma unroll
            for (int mt = 0; mt < 4; mt++)
#pragma unroll
                for (int nt = 0; nt < 4; nt++) {
                    mma_bf16(acc[mt][nt], aH[mt], bH[nt]);
                    mma_bf16(acc[mt][nt], aH[mt], bL[nt]);
                    mma_bf16(acc[mt][nt], aL[mt], bH[nt]);
                }
        }

        // epilogue: mine v = sq_j - 2*dot
        const float* sqS  = (const float*)(smem + SM_SQ(b));
        const int*   labS = (const int*)  (smem + SM_LAB(b));
#pragma unroll
        for (int nt = 0; nt < 4; nt++) {
            int nl0 = wn * 32 + nt * 8 + 2 * (lane & 3);
            float sq0 = sqS[nl0], sq1 = sqS[nl0 + 1];
            int   lb0 = labS[nl0], lb1 = labS[nl0 + 1];
#pragma unroll
            for (int mt = 0; mt < 4; mt++) {
#pragma unroll
                for (int h = 0; h < 2; h++) {
                    float v0 = fmaf(-2.0f, acc[mt][nt][2 * h],     sq0);
                    float v1 = fmaf(-2.0f, acc[mt][nt][2 * h + 1], sq1);
                    int rl = rowlab[mt][h];
                    if (rl == lb0) vmax[mt][h] = fmaxf(vmax[mt][h], v0);
                    else           vmin[mt][h] = fminf(vmin[mt][h], v0);
                    if (rl == lb1) vmax[mt][h] = fmaxf(vmax[mt][h], v1);
                    else           vmin[mt][h] = fminf(vmin[mt][h], v1);
                }
            }
        }

        if (jt + 1 < NTILES) CP_WAIT0();
        __syncthreads();
    }

    // ---- reduction: across lane%4 (same row), then across wn warps ----
#pragma unroll
    for (int mt = 0; mt < 4; mt++)
#pragma unroll
        for (int h = 0; h < 2; h++) {
#pragma unroll
            for (int off = 1; off <= 2; off <<= 1) {
                vmax[mt][h] = fmaxf(vmax[mt][h], __shfl_xor_sync(0xffffffffu, vmax[mt][h], off));
                vmin[mt][h] = fminf(vmin[mt][h], __shfl_xor_sync(0xffffffffu, vmin[mt][h], off));
            }
        }
    float* redmax = (float*)(smem + SM_RED);          // [4][128]
    float* redmin = redmax + 4 * 128;
    if ((lane & 3) == 0) {
#pragma unroll
        for (int mt = 0; mt < 4; mt++)
#pragma unroll
            for (int h = 0; h < 2; h++) {
                int rl = wm * 64 + mt * 16 + h * 8 + (lane >> 2);
                redmax[wn * 128 + rl] = vmax[mt][h];
                redmin[wn * 128 + rl] = vmin[mt][h];
            }
    }
    __syncthreads();
    if (tid < BM) {
        float mx = -FLT_MAX, mn = FLT_MAX;
#pragma unroll
        for (int w = 0; w < 4; w++) {
            mx = fmaxf(mx, redmax[w * 128 + tid]);
            mn = fminf(mn, redmin[w * 128 + tid]);
        }
        g_vmaxpos[split][rowBase + tid] = mx;
        g_vminneg[split][rowBase + tid] = mn;
    }
}

// ---------------------------------------------------------------------------
// Kernel 3: combine splits, per-anchor loss, AvgNonZero reduction.
__global__ void finalize_kernel(float* __restrict__ out) {
    __shared__ float ssum[1024];
    __shared__ int   scnt[1024];
    int t = threadIdx.x;
    float sum = 0.0f;
    int   cnt = 0;
    for (int i = t; i < N; i += 1024) {
        float mp = fmaxf(g_vmaxpos[0][i], g_vmaxpos[1][i]);
        float mn = fminf(g_vminneg[0][i], g_vminneg[1][i]);
        float sqi = g_sq[i];
        float dap = sqrtf(fmaxf(sqi + mp, 0.0f));
        float dan = sqrtf(fmaxf(sqi + mn, 0.0f));
        float per = fmaxf(dap - dan + MARGIN, 0.0f);
        if (per > 0.0f) { sum += per; cnt++; }
    }
    ssum[t] = sum; scnt[t] = cnt;
    __syncthreads();
    for (int o = 512; o; o >>= 1) {
        if (t < o) { ssum[t] += ssum[t + o]; scnt[t] += scnt[t + o]; }
        __syncthreads();
    }
    if (t == 0) out[0] = (scnt[0] > 0) ? (ssum[0] / (float)scnt[0]) : 0.0f;
}

// ---------------------------------------------------------------------------
extern "C" void kernel_launch(void* const* d_in, const int* in_sizes, int n_in,
                              void* d_out, int out_size) {
    const float* x      = (const float*)d_in[0];
    const int*   labels = (const int*)d_in[1];

    normalize_kernel<<<N / 8, 256>>>(x);

    cudaFuncSetAttribute(tile_kernel,
                         cudaFuncAttributeMaxDynamicSharedMemorySize, SM_TOTAL);
    tile_kernel<<<dim3(N / BM, NSPLIT), 256, SM_TOTAL>>>(labels);

    finalize_kernel<<<1, 1024>>>((float*)d_out);
}

// round 5
// speedup vs baseline: 4.4032x; 1.5485x over previous
#include <cuda_runtime.h>
#include <cuda_fp16.h>
#include <math.h>
#include <float.h>
#include <stdint.h>

#define N 8192
#define D 128
#define BM 128
#define BN 128
#define NROWT (N / BM)        // 64
#define NCOLT (N / BN)        // 64
#define TOT_TILES (NROWT * NCOLT)
#define NCTA 148
#define TBASE (TOT_TILES / NCTA)        // 27
#define TREM  (TOT_TILES - TBASE * NCTA) // 100
#define MARGIN 0.05f
#define TS 272                // smem tile row stride bytes (128 fp16 + 8 pad)

// ---------------- device scratch ----------------
__device__ __half g_hi[N * D];
__device__ __half g_lo[N * D];
__device__ float g_sq[N];
__device__ unsigned g_vmax_u[N];   // ordered-uint encoded float max (positives)
__device__ unsigned g_vmin_u[N];   // ordered-uint encoded float min (negatives)

// ---------------- smem layout (bytes) ----------------
#define TILE_BYTES (128 * TS)                 // 34816
#define SM_A_HI    0
#define SM_A_LO    TILE_BYTES
#define SM_B(b)    (2 * TILE_BYTES + (b) * TILE_BYTES)
#define SM_SQ(b)   (4 * TILE_BYTES + (b) * 512)
#define SM_LAB(b)  (4 * TILE_BYTES + 1024 + (b) * 512)
#define SM_RED     (4 * TILE_BYTES + 2048)    // redmax[4][128], redmin[4][128]
#define SM_TOTAL   (SM_RED + 4096)

__device__ __forceinline__ uint32_t smem_u32(const void* p) {
    uint32_t a;
    asm("{ .reg .u64 t; cvta.to.shared.u64 t, %1; cvt.u32.u64 %0, t; }" : "=r"(a) : "l"(p));
    return a;
}
#define CP16(dst, src) \
    asm volatile("cp.async.cg.shared.global [%0], [%1], 16;" :: "r"(dst), "l"(src) : "memory")
#define CP_COMMIT() asm volatile("cp.async.commit_group;" ::: "memory")
#define CP_WAIT0()  asm volatile("cp.async.wait_group 0;" ::: "memory")

__device__ __forceinline__ void ldm_x4(uint32_t* r, uint32_t addr) {
    asm volatile("ldmatrix.sync.aligned.m8n8.x4.shared.b16 {%0,%1,%2,%3}, [%4];"
                 : "=r"(r[0]), "=r"(r[1]), "=r"(r[2]), "=r"(r[3]) : "r"(addr));
}
__device__ __forceinline__ void ldm_x2(uint32_t* r, uint32_t addr) {
    asm volatile("ldmatrix.sync.aligned.m8n8.x2.shared.b16 {%0,%1}, [%2];"
                 : "=r"(r[0]), "=r"(r[1]) : "r"(addr));
}
__device__ __forceinline__ void mma_f16(float* c, const uint32_t* a, const uint32_t* b) {
    asm volatile(
        "mma.sync.aligned.m16n8k16.row.col.f32.f16.f16.f32 "
        "{%0,%1,%2,%3}, {%4,%5,%6,%7}, {%8,%9}, {%0,%1,%2,%3};"
        : "+f"(c[0]), "+f"(c[1]), "+f"(c[2]), "+f"(c[3])
        : "r"(a[0]), "r"(a[1]), "r"(a[2]), "r"(a[3]), "r"(b[0]), "r"(b[1]));
}

// monotone float <-> uint mapping for atomic max/min on floats of any sign
__device__ __forceinline__ unsigned f2ord(float f) {
    unsigned b = __float_as_uint(f);
    return (b & 0x80000000u) ? ~b : (b | 0x80000000u);
}
__device__ __forceinline__ float ord2f(unsigned u) {
    unsigned b = (u & 0x80000000u) ? (u ^ 0x80000000u) : ~u;
    return __uint_as_float(b);
}

// ---------------------------------------------------------------------------
// Kernel 1: normalize rows -> fp16 hi/lo split + fp32 sumsq; init atomic arrays.
__global__ void normalize_kernel(const float* __restrict__ x) {
    int row  = blockIdx.x * 8 + (threadIdx.x >> 5);
    int lane = threadIdx.x & 31;
    float4 v = ((const float4*)(x + (size_t)row * D))[lane];
    float s = v.x * v.x + v.y * v.y + v.z * v.z + v.w * v.w;
#pragma unroll
    for (int o = 16; o; o >>= 1) s += __shfl_xor_sync(0xffffffffu, s, o);
    float r = 1.0f / fmaxf(sqrtf(s), 1e-12f);
    float o4[4] = {v.x * r, v.y * r, v.z * r, v.w * r};
    float s2 = o4[0]*o4[0] + o4[1]*o4[1] + o4[2]*o4[2] + o4[3]*o4[3];
#pragma unroll
    for (int o = 16; o; o >>= 1) s2 += __shfl_xor_sync(0xffffffffu, s2, o);
    if (lane == 0) {
        g_sq[row] = s2;
        g_vmax_u[row] = f2ord(-FLT_MAX);
        g_vmin_u[row] = f2ord(FLT_MAX);
    }
    uint32_t hp[2], lp[2];
#pragma unroll
    for (int i = 0; i < 2; i++) {
        __half h0 = __float2half_rn(o4[2*i]);
        __half h1 = __float2half_rn(o4[2*i+1]);
        __half l0 = __float2half_rn(o4[2*i]   - __half2float(h0));
        __half l1 = __float2half_rn(o4[2*i+1] - __half2float(h1));
        hp[i] = (uint32_t)__half_as_ushort(h0) | ((uint32_t)__half_as_ushort(h1) << 16);
        lp[i] = (uint32_t)__half_as_ushort(l0) | ((uint32_t)__half_as_ushort(l1) << 16);
    }
    ((uint2*)(g_hi + (size_t)row * D))[lane] = make_uint2(hp[0], hp[1]);
    ((uint2*)(g_lo + (size_t)row * D))[lane] = make_uint2(lp[0], lp[1]);
}

// ---------------------------------------------------------------------------
// Kernel 2: persistent fused GEMM + batch-hard mining.
// 148 CTAs, each owns a contiguous range of the 4096 (row,col) tiles.
// dot = aHi*bHi + aLo*bHi  (A split to fp16 hi/lo; B hi only).
__global__ __launch_bounds__(256, 1)
void tile_kernel(const int* __restrict__ labels) {
    extern __shared__ char smem[];
    const uint32_t sb = smem_u32(smem);
    const int tid  = threadIdx.x;
    const int lane = tid & 31;
    const int wid  = tid >> 5;
    const int wm   = wid & 1;      // 2 warp rows (64 each)
    const int wn   = wid >> 1;     // 4 warp cols (32 each)
    const int bid  = blockIdx.x;

    const int start = bid * TBASE + min(bid, TREM);
    const int tend  = start + TBASE + (bid < TREM ? 1 : 0);

    // ldmatrix lane addresses (same mapping as the verified R4 kernel)
    const uint32_t aLane = (uint32_t)((wm * 64 + (lane & 7) + ((lane >> 3) & 1) * 8) * TS
                                      + (lane >> 4) * 16);
    const int lane16 = lane & 15;
    const uint32_t bLane = (uint32_t)((wn * 32 + (lane16 & 7)) * TS + (lane16 >> 3) * 16);

    auto loadA = [&](int rowBase) {
        const char* sH = (const char*)g_hi + (size_t)rowBase * D * 2;
        const char* sL = (const char*)g_lo + (size_t)rowBase * D * 2;
#pragma unroll
        for (int i = 0; i < 8; i++) {
            int q = tid + i * 256;
            int r = q >> 4, kc = q & 15;
            uint32_t off = r * TS + kc * 16;
            size_t   go  = (size_t)r * 256 + kc * 16;
            CP16(sb + SM_A_HI + off, sH + go);
            CP16(sb + SM_A_LO + off, sL + go);
        }
    };
    auto loadB = [&](int ct, int b) {
        int colBase = ct * BN;
        const char* sH = (const char*)g_hi + (size_t)colBase * D * 2;
#pragma unroll
        for (int i = 0; i < 8; i++) {
            int q = tid + i * 256;
            int r = q >> 4, kc = q & 15;
            CP16(sb + SM_B(b) + r * TS + kc * 16, sH + (size_t)r * 256 + kc * 16);
        }
        if (tid < BN) {
            *(float*)(smem + SM_SQ(b)  + tid * 4) = g_sq[colBase + tid];
            *(int*)  (smem + SM_LAB(b) + tid * 4) = labels[colBase + tid];
        }
        CP_COMMIT();
    };

    int t = start;
    while (t < tend) {
        const int rt = t >> 6;
        const int rowBase = rt * BM;
        const int segEnd = min(tend, (rt + 1) * NCOLT);

        loadA(rowBase);
        loadB(t & 63, 0);
        CP_WAIT0();
        __syncthreads();

        int rowlab[4][2];
#pragma unroll
        for (int mt = 0; mt < 4; mt++)
#pragma unroll
            for (int h = 0; h < 2; h++)
                rowlab[mt][h] = labels[rowBase + wm * 64 + mt * 16 + h * 8 + (lane >> 2)];

        float vmax[4][2], vmin[4][2];
#pragma unroll
        for (int mt = 0; mt < 4; mt++)
#pragma unroll
            for (int h = 0; h < 2; h++) { vmax[mt][h] = -FLT_MAX; vmin[mt][h] = FLT_MAX; }

        for (int tt = t; tt < segEnd; tt++) {
            const int b = (tt - t) & 1;
            if (tt + 1 < segEnd) loadB((tt + 1) & 63, b ^ 1);

            float acc[4][4][4];
#pragma unroll
            for (int mt = 0; mt < 4; mt++)
#pragma unroll
                for (int nt = 0; nt < 4; nt++)
#pragma unroll
                    for (int i = 0; i < 4; i++) acc[mt][nt][i] = 0.0f;

            const uint32_t AH = sb + SM_A_HI, AL = sb + SM_A_LO, BB = sb + SM_B(b);
#pragma unroll
            for (int ks = 0; ks < 8; ks++) {
                uint32_t aH[4][4], aL[4][4], bH[4][2];
#pragma unroll
                for (int mt = 0; mt < 4; mt++) {
                    uint32_t off = aLane + (uint32_t)(mt * 16 * TS + ks * 32);
                    ldm_x4(aH[mt], AH + off);
                    ldm_x4(aL[mt], AL + off);
                }
#pragma unroll
                for (int nt = 0; nt < 4; nt++)
                    ldm_x2(bH[nt], BB + bLane + (uint32_t)(nt * 8 * TS + ks * 32));
#pragma unroll
                for (int mt = 0; mt < 4; mt++)
#pragma unroll
                    for (int nt = 0; nt < 4; nt++) {
                        mma_f16(acc[mt][nt], aH[mt], bH[nt]);
                        mma_f16(acc[mt][nt], aL[mt], bH[nt]);
                    }
            }

            // epilogue: mine v = sq_j - 2*dot
            const float* sqS  = (const float*)(smem + SM_SQ(b));
            const int*   labS = (const int*)  (smem + SM_LAB(b));
#pragma unroll
            for (int nt = 0; nt < 4; nt++) {
                int nl0 = wn * 32 + nt * 8 + 2 * (lane & 3);
                float sq0 = sqS[nl0], sq1 = sqS[nl0 + 1];
                int   lb0 = labS[nl0], lb1 = labS[nl0 + 1];
#pragma unroll
                for (int mt = 0; mt < 4; mt++)
#pragma unroll
                    for (int h = 0; h < 2; h++) {
                        float v0 = fmaf(-2.0f, acc[mt][nt][2 * h],     sq0);
                        float v1 = fmaf(-2.0f, acc[mt][nt][2 * h + 1], sq1);
                        int rl = rowlab[mt][h];
                        if (rl == lb0) vmax[mt][h] = fmaxf(vmax[mt][h], v0);
                        else           vmin[mt][h] = fminf(vmin[mt][h], v0);
                        if (rl == lb1) vmax[mt][h] = fmaxf(vmax[mt][h], v1);
                        else           vmin[mt][h] = fminf(vmin[mt][h], v1);
                    }
            }

            if (tt + 1 < segEnd) CP_WAIT0();
            __syncthreads();
        }

        // flush this row tile's mining results
#pragma unroll
        for (int mt = 0; mt < 4; mt++)
#pragma unroll
            for (int h = 0; h < 2; h++)
#pragma unroll
                for (int off = 1; off <= 2; off <<= 1) {
                    vmax[mt][h] = fmaxf(vmax[mt][h], __shfl_xor_sync(0xffffffffu, vmax[mt][h], off));
                    vmin[mt][h] = fminf(vmin[mt][h], __shfl_xor_sync(0xffffffffu, vmin[mt][h], off));
                }
        float* redmax = (float*)(smem + SM_RED);
        float* redmin = redmax + 4 * 128;
        if ((lane & 3) == 0) {
#pragma unroll
            for (int mt = 0; mt < 4; mt++)
#pragma unroll
                for (int h = 0; h < 2; h++) {
                    int rl = wm * 64 + mt * 16 + h * 8 + (lane >> 2);
                    redmax[wn * 128 + rl] = vmax[mt][h];
                    redmin[wn * 128 + rl] = vmin[mt][h];
                }
        }
        __syncthreads();
        if (tid < BM) {
            float mx = -FLT_MAX, mn = FLT_MAX;
#pragma unroll
            for (int w = 0; w < 4; w++) {
                mx = fmaxf(mx, redmax[w * 128 + tid]);
                mn = fminf(mn, redmin[w * 128 + tid]);
            }
            atomicMax(&g_vmax_u[rowBase + tid], f2ord(mx));
            atomicMin(&g_vmin_u[rowBase + tid], f2ord(mn));
        }
        __syncthreads();
        t = segEnd;
    }
}

// ---------------------------------------------------------------------------
// Kernel 3: per-anchor loss + AvgNonZero reduction.
__global__ void finalize_kernel(float* __restrict__ out) {
    __shared__ float ssum[1024];
    __shared__ int   scnt[1024];
    int t = threadIdx.x;
    float sum = 0.0f;
    int   cnt = 0;
    for (int i = t; i < N; i += 1024) {
        float mp = ord2f(g_vmax_u[i]);
        float mn = ord2f(g_vmin_u[i]);
        float sqi = g_sq[i];
        float dap = sqrtf(fmaxf(sqi + mp, 0.0f));
        float dan = sqrtf(fmaxf(sqi + mn, 0.0f));
        float per = fmaxf(dap - dan + MARGIN, 0.0f);
        if (per > 0.0f) { sum += per; cnt++; }
    }
    ssum[t] = sum; scnt[t] = cnt;
    __syncthreads();
    for (int o = 512; o; o >>= 1) {
        if (t < o) { ssum[t] += ssum[t + o]; scnt[t] += scnt[t + o]; }
        __syncthreads();
    }
    if (t == 0) out[0] = (scnt[0] > 0) ? (ssum[0] / (float)scnt[0]) : 0.0f;
}

// ---------------------------------------------------------------------------
extern "C" void kernel_launch(void* const* d_in, const int* in_sizes, int n_in,
                              void* d_out, int out_size) {
    const float* x      = (const float*)d_in[0];
    const int*   labels = (const int*)d_in[1];

    normalize_kernel<<<N / 8, 256>>>(x);

    cudaFuncSetAttribute(tile_kernel,
                         cudaFuncAttributeMaxDynamicSharedMemorySize, SM_TOTAL);
    tile_kernel<<<NCTA, 256, SM_TOTAL>>>(labels);

    finalize_kernel<<<1, 1024>>>((float*)d_out);
}

// round 6
// speedup vs baseline: 6.1704x; 1.4013x over previous
#include <cuda_runtime.h>
#include <cuda_fp16.h>
#include <math.h>
#include <float.h>
#include <stdint.h>

#define N 8192
#define D 128
#define BM 128
#define BN 128
#define NBLK (N / BM)                         // 64
#define TOT_TILES (NBLK * (NBLK + 1) / 2)     // 2080 upper-triangular tiles
#define NCTA 148
#define TBASE (TOT_TILES / NCTA)              // 14
#define TREM  (TOT_TILES - TBASE * NCTA)      // 8
#define MARGIN 0.05f
#define TS 272                // smem tile row stride bytes (128 fp16 + 8 pad)

// ---------------- device scratch ----------------
__device__ __half g_hi[N * D];
__device__ __half g_lo[N * D];
__device__ float g_sq[N];
__device__ unsigned g_vmax_u[N];   // ordered-uint float max (positives)
__device__ unsigned g_vmin_u[N];   // ordered-uint float min (negatives)

// ---------------- smem layout (bytes) ----------------
#define TILE_BYTES (128 * TS)                 // 34816
#define SM_A_HI    0
#define SM_A_LO    TILE_BYTES
#define SM_B(b)    (2 * TILE_BYTES + (b) * TILE_BYTES)
#define SM_SQ(b)   (4 * TILE_BYTES + (b) * 512)
#define SM_LAB(b)  (4 * TILE_BYTES + 1024 + (b) * 512)
#define SM_RED     (4 * TILE_BYTES + 2048)    // redmax[4][128], redmin[4][128]
#define SM_TOTAL   (SM_RED + 4096)

__device__ __forceinline__ uint32_t smem_u32(const void* p) {
    uint32_t a;
    asm("{ .reg .u64 t; cvta.to.shared.u64 t, %1; cvt.u32.u64 %0, t; }" : "=r"(a) : "l"(p));
    return a;
}
#define CP16(dst, src) \
    asm volatile("cp.async.cg.shared.global [%0], [%1], 16;" :: "r"(dst), "l"(src) : "memory")
#define CP_COMMIT() asm volatile("cp.async.commit_group;" ::: "memory")
#define CP_WAIT0()  asm volatile("cp.async.wait_group 0;" ::: "memory")

__device__ __forceinline__ void ldm_x4(uint32_t* r, uint32_t addr) {
    asm volatile("ldmatrix.sync.aligned.m8n8.x4.shared.b16 {%0,%1,%2,%3}, [%4];"
                 : "=r"(r[0]), "=r"(r[1]), "=r"(r[2]), "=r"(r[3]) : "r"(addr));
}
__device__ __forceinline__ void ldm_x2(uint32_t* r, uint32_t addr) {
    asm volatile("ldmatrix.sync.aligned.m8n8.x2.shared.b16 {%0,%1}, [%2];"
                 : "=r"(r[0]), "=r"(r[1]) : "r"(addr));
}
__device__ __forceinline__ void mma_f16(float* c, const uint32_t* a, const uint32_t* b) {
    asm volatile(
        "mma.sync.aligned.m16n8k16.row.col.f32.f16.f16.f32 "
        "{%0,%1,%2,%3}, {%4,%5,%6,%7}, {%8,%9}, {%0,%1,%2,%3};"
        : "+f"(c[0]), "+f"(c[1]), "+f"(c[2]), "+f"(c[3])
        : "r"(a[0]), "r"(a[1]), "r"(a[2]), "r"(a[3]), "r"(b[0]), "r"(b[1]));
}

__device__ __forceinline__ unsigned f2ord(float f) {
    unsigned b = __float_as_uint(f);
    return (b & 0x80000000u) ? ~b : (b | 0x80000000u);
}
__device__ __forceinline__ float ord2f(unsigned u) {
    unsigned b = (u & 0x80000000u) ? (u ^ 0x80000000u) : ~u;
    return __uint_as_float(b);
}
// tiles with row-block < r:
__device__ __forceinline__ int cumt(int r) { return r * NBLK - (r * (r - 1)) / 2; }

// ---------------------------------------------------------------------------
// Kernel 1: normalize rows -> fp16 hi/lo split + fp32 sumsq; init atomics.
__global__ void normalize_kernel(const float* __restrict__ x) {
    int row  = blockIdx.x * 8 + (threadIdx.x >> 5);
    int lane = threadIdx.x & 31;
    float4 v = ((const float4*)(x + (size_t)row * D))[lane];
    float s = v.x * v.x + v.y * v.y + v.z * v.z + v.w * v.w;
#pragma unroll
    for (int o = 16; o; o >>= 1) s += __shfl_xor_sync(0xffffffffu, s, o);
    float r = 1.0f / fmaxf(sqrtf(s), 1e-12f);
    float o4[4] = {v.x * r, v.y * r, v.z * r, v.w * r};
    float s2 = o4[0]*o4[0] + o4[1]*o4[1] + o4[2]*o4[2] + o4[3]*o4[3];
#pragma unroll
    for (int o = 16; o; o >>= 1) s2 += __shfl_xor_sync(0xffffffffu, s2, o);
    if (lane == 0) {
        g_sq[row] = s2;
        g_vmax_u[row] = f2ord(-FLT_MAX);
        g_vmin_u[row] = f2ord(FLT_MAX);
    }
    uint32_t hp[2], lp[2];
#pragma unroll
    for (int i = 0; i < 2; i++) {
        __half h0 = __float2half_rn(o4[2*i]);
        __half h1 = __float2half_rn(o4[2*i+1]);
        __half l0 = __float2half_rn(o4[2*i]   - __half2float(h0));
        __half l1 = __float2half_rn(o4[2*i+1] - __half2float(h1));
        hp[i] = (uint32_t)__half_as_ushort(h0) | ((uint32_t)__half_as_ushort(h1) << 16);
        lp[i] = (uint32_t)__half_as_ushort(l0) | ((uint32_t)__half_as_ushort(l1) << 16);
    }
    ((uint2*)(g_hi + (size_t)row * D))[lane] = make_uint2(hp[0], hp[1]);
    ((uint2*)(g_lo + (size_t)row * D))[lane] = make_uint2(lp[0], lp[1]);
}

// ---------------------------------------------------------------------------
// Kernel 2: persistent fused GEMM + batch-hard mining over the UPPER TRIANGLE
// of the 64x64 tile grid. Off-diagonal tiles mine both directions.
__global__ __launch_bounds__(256, 1)
void tile_kernel(const int* __restrict__ labels) {
    extern __shared__ char smem[];
    const uint32_t sb = smem_u32(smem);
    const int tid  = threadIdx.x;
    const int lane = tid & 31;
    const int wid  = tid >> 5;
    const int wm   = wid & 1;      // 2 warp rows (64 each)
    const int wn   = wid >> 1;     // 4 warp cols (32 each)
    const int bid  = blockIdx.x;

    const int start = bid * TBASE + min(bid, TREM);
    const int tend  = start + TBASE + (bid < TREM ? 1 : 0);

    const uint32_t aLane = (uint32_t)((wm * 64 + (lane & 7) + ((lane >> 3) & 1) * 8) * TS
                                      + (lane >> 4) * 16);
    const int lane16 = lane & 15;
    const uint32_t bLane = (uint32_t)((wn * 32 + (lane16 & 7)) * TS + (lane16 >> 3) * 16);

    auto loadA = [&](int rowBase) {
        const char* sH = (const char*)g_hi + (size_t)rowBase * D * 2;
        const char* sL = (const char*)g_lo + (size_t)rowBase * D * 2;
#pragma unroll
        for (int i = 0; i < 8; i++) {
            int q = tid + i * 256;
            int r = q >> 4, kc = q & 15;
            uint32_t off = r * TS + kc * 16;
            size_t   go  = (size_t)r * 256 + kc * 16;
            CP16(sb + SM_A_HI + off, sH + go);
            CP16(sb + SM_A_LO + off, sL + go);
        }
    };
    auto loadB = [&](int ct, int b) {
        int colBase = ct * BN;
        const char* sH = (const char*)g_hi + (size_t)colBase * D * 2;
#pragma unroll
        for (int i = 0; i < 8; i++) {
            int q = tid + i * 256;
            int r = q >> 4, kc = q & 15;
            CP16(sb + SM_B(b) + r * TS + kc * 16, sH + (size_t)r * 256 + kc * 16);
        }
        if (tid < BN) {
            *(float*)(smem + SM_SQ(b)  + tid * 4) = g_sq[colBase + tid];
            *(int*)  (smem + SM_LAB(b) + tid * 4) = labels[colBase + tid];
        }
        CP_COMMIT();
    };

    int t = start;
    int rt = 0;
    while (cumt(rt + 1) <= t) rt++;

    while (t < tend) {
        const int rowBase = rt * BM;
        const int segEnd = min(tend, cumt(rt + 1));
        const int ct0 = rt + (t - cumt(rt));

        loadA(rowBase);
        loadB(ct0, 0);
        CP_WAIT0();
        __syncthreads();

        int   rowlab[4][2];
        float sqRow[4][2];
#pragma unroll
        for (int mt = 0; mt < 4; mt++)
#pragma unroll
            for (int h = 0; h < 2; h++) {
                int rg = rowBase + wm * 64 + mt * 16 + h * 8 + (lane >> 2);
                rowlab[mt][h] = labels[rg];
                sqRow[mt][h]  = g_sq[rg];
            }

        float vmax[4][2], vmin[4][2];
#pragma unroll
        for (int mt = 0; mt < 4; mt++)
#pragma unroll
            for (int h = 0; h < 2; h++) { vmax[mt][h] = -FLT_MAX; vmin[mt][h] = FLT_MAX; }

        for (int tt = t; tt < segEnd; tt++) {
            const int ct = rt + (tt - cumt(rt));
            const int b  = (tt - t) & 1;
            const bool offDiag = (ct != rt);
            if (tt + 1 < segEnd) loadB(ct + 1, b ^ 1);

            float acc[4][4][4];
#pragma unroll
            for (int mt = 0; mt < 4; mt++)
#pragma unroll
                for (int nt = 0; nt < 4; nt++)
#pragma unroll
                    for (int i = 0; i < 4; i++) acc[mt][nt][i] = 0.0f;

            const uint32_t AH = sb + SM_A_HI, AL = sb + SM_A_LO, BB = sb + SM_B(b);
#pragma unroll
            for (int ks = 0; ks < 8; ks++) {
                uint32_t aH[4][4], aL[4][4], bH[4][2];
#pragma unroll
                for (int mt = 0; mt < 4; mt++) {
                    uint32_t off = aLane + (uint32_t)(mt * 16 * TS + ks * 32);
                    ldm_x4(aH[mt], AH + off);
                    ldm_x4(aL[mt], AL + off);
                }
#pragma unroll
                for (int nt = 0; nt < 4; nt++)
                    ldm_x2(bH[nt], BB + bLane + (uint32_t)(nt * 8 * TS + ks * 32));
#pragma unroll
                for (int mt = 0; mt < 4; mt++)
#pragma unroll
                    for (int nt = 0; nt < 4; nt++) {
                        mma_f16(acc[mt][nt], aH[mt], bH[nt]);
                        mma_f16(acc[mt][nt], aL[mt], bH[nt]);
                    }
            }

            // epilogue: row mining (v = sq_col - 2dot) + col mining (v = sq_row - 2dot)
            const float* sqS  = (const float*)(smem + SM_SQ(b));
            const int*   labS = (const int*)  (smem + SM_LAB(b));
            float cmax[4][2], cmin[4][2];
#pragma unroll
            for (int nt = 0; nt < 4; nt++)
#pragma unroll
                for (int c = 0; c < 2; c++) { cmax[nt][c] = -FLT_MAX; cmin[nt][c] = FLT_MAX; }

#pragma unroll
            for (int nt = 0; nt < 4; nt++) {
                int nl0 = wn * 32 + nt * 8 + 2 * (lane & 3);
                float sq0 = sqS[nl0], sq1 = sqS[nl0 + 1];
                int   lb0 = labS[nl0], lb1 = labS[nl0 + 1];
#pragma unroll
                for (int mt = 0; mt < 4; mt++)
#pragma unroll
                    for (int h = 0; h < 2; h++) {
                        float m0 = -2.0f * acc[mt][nt][2 * h];
                        float m1 = -2.0f * acc[mt][nt][2 * h + 1];
                        int   rl = rowlab[mt][h];
                        float sr = sqRow[mt][h];
                        if (rl == lb0) {
                            vmax[mt][h]  = fmaxf(vmax[mt][h],  m0 + sq0);
                            cmax[nt][0]  = fmaxf(cmax[nt][0],  m0 + sr);
                        } else {
                            vmin[mt][h]  = fminf(vmin[mt][h],  m0 + sq0);
                            cmin[nt][0]  = fminf(cmin[nt][0],  m0 + sr);
                        }
                        if (rl == lb1) {
                            vmax[mt][h]  = fmaxf(vmax[mt][h],  m1 + sq1);
                            cmax[nt][1]  = fmaxf(cmax[nt][1],  m1 + sr);
                        } else {
                            vmin[mt][h]  = fminf(vmin[mt][h],  m1 + sq1);
                            cmin[nt][1]  = fminf(cmin[nt][1],  m1 + sr);
                        }
                    }
            }

            if (offDiag) {
                // reduce col accumulators over rows (lane bits 2..4), then REDG
#pragma unroll
                for (int nt = 0; nt < 4; nt++)
#pragma unroll
                    for (int c = 0; c < 2; c++) {
#pragma unroll
                        for (int off = 4; off <= 16; off <<= 1) {
                            cmax[nt][c] = fmaxf(cmax[nt][c], __shfl_xor_sync(0xffffffffu, cmax[nt][c], off));
                            cmin[nt][c] = fminf(cmin[nt][c], __shfl_xor_sync(0xffffffffu, cmin[nt][c], off));
                        }
                    }
                if (lane < 4) {
                    int colBase = ct * BN;
#pragma unroll
                    for (int nt = 0; nt < 4; nt++)
#pragma unroll
                        for (int c = 0; c < 2; c++) {
                            int cg = colBase + wn * 32 + nt * 8 + 2 * lane + c;
                            atomicMax(&g_vmax_u[cg], f2ord(cmax[nt][c]));
                            atomicMin(&g_vmin_u[cg], f2ord(cmin[nt][c]));
                        }
                }
            }

            if (tt + 1 < segEnd) CP_WAIT0();
            __syncthreads();
        }

        // flush row-anchor accumulators for this rt segment
#pragma unroll
        for (int mt = 0; mt < 4; mt++)
#pragma unroll
            for (int h = 0; h < 2; h++)
#pragma unroll
                for (int off = 1; off <= 2; off <<= 1) {
                    vmax[mt][h] = fmaxf(vmax[mt][h], __shfl_xor_sync(0xffffffffu, vmax[mt][h], off));
                    vmin[mt][h] = fminf(vmin[mt][h], __shfl_xor_sync(0xffffffffu, vmin[mt][h], off));
                }
        float* redmax = (float*)(smem + SM_RED);
        float* redmin = redmax + 4 * 128;
        if ((lane & 3) == 0) {
#pragma unroll
            for (int mt = 0; mt < 4; mt++)
#pragma unroll
                for (int h = 0; h < 2; h++) {
                    int rl = wm * 64 + mt * 16 + h * 8 + (lane >> 2);
                    redmax[wn * 128 + rl] = vmax[mt][h];
                    redmin[wn * 128 + rl] = vmin[mt][h];
                }
        }
        __syncthreads();
        if (tid < BM) {
            float mx = -FLT_MAX, mn = FLT_MAX;
#pragma unroll
            for (int w = 0; w < 4; w++) {
                mx = fmaxf(mx, redmax[w * 128 + tid]);
                mn = fminf(mn, redmin[w * 128 + tid]);
            }
            atomicMax(&g_vmax_u[rowBase + tid], f2ord(mx));
            atomicMin(&g_vmin_u[rowBase + tid], f2ord(mn));
        }
        __syncthreads();
        t = segEnd;
        rt++;
    }
}

// ---------------------------------------------------------------------------
// Kernel 3: per-anchor loss + AvgNonZero reduction.
__global__ void finalize_kernel(float* __restrict__ out) {
    __shared__ float ssum[1024];
    __shared__ int   scnt[1024];
    int t = threadIdx.x;
    float sum = 0.0f;
    int   cnt = 0;
    for (int i = t; i < N; i += 1024) {
        float mp = ord2f(g_vmax_u[i]);
        float mn = ord2f(g_vmin_u[i]);
        float sqi = g_sq[i];
        float dap = sqrtf(fmaxf(sqi + mp, 0.0f));
        float dan = sqrtf(fmaxf(sqi + mn, 0.0f));
        float per = fmaxf(dap - dan + MARGIN, 0.0f);
        if (per > 0.0f) { sum += per; cnt++; }
    }
    ssum[t] = sum; scnt[t] = cnt;
    __syncthreads();
    for (int o = 512; o; o >>= 1) {
        if (t < o) { ssum[t] += ssum[t + o]; scnt[t] += scnt[t + o]; }
        __syncthreads();
    }
    if (t == 0) out[0] = (scnt[0] > 0) ? (ssum[0] / (float)scnt[0]) : 0.0f;
}

// ---------------------------------------------------------------------------
extern "C" void kernel_launch(void* const* d_in, const int* in_sizes, int n_in,
                              void* d_out, int out_size) {
    const float* x      = (const float*)d_in[0];
    const int*   labels = (const int*)d_in[1];

    normalize_kernel<<<N / 8, 256>>>(x);

    cudaFuncSetAttribute(tile_kernel,
                         cudaFuncAttributeMaxDynamicSharedMemorySize, SM_TOTAL);
    tile_kernel<<<NCTA, 256, SM_TOTAL>>>(labels);

    finalize_kernel<<<1, 1024>>>((float*)d_out);
}